// round 13
// baseline (speedup 1.0000x reference)
#include <cuda_runtime.h>
#include <cuda_fp16.h>
#include <cstdint>

// ---------------------------------------------------------------------------
// BayesianNN (sm_103 target, legacy mma path):
// out[s] = L2( tanh(L1( tanh(L0(x)) )) ),  Li: h @ (z_w*e^ls + m) + bias
// S=32, B=2048, dims 256 -> 512 -> 512 -> 64, fp32 in/out.
//
// Round 13: precompute sig=exp(log_std) ONCE (sample-independent!) instead of
// recomputing it 32x inside pack_w -> removes ~16M redundant MUFU ops that
// dominated pack time (~75us -> ~25us predicted). GEMM path unchanged from
// round 12 (fp16 fragment-packed, K=64 stages, fused L2 with red.v2.f32).
// ---------------------------------------------------------------------------

#define NS 32
#define BATCH 2048

__device__ __align__(1024) __half g_h0[(size_t)NS * BATCH * 512];  // 64 MB
__device__ __align__(1024) __half g_xpk[BATCH * 256];              // 1 MB
__device__ __align__(1024) __half g_wt0[NS * 256 * 512];           // 8 MB
__device__ __align__(1024) __half g_wt1[NS * 512 * 512];           // 16 MB
__device__ __align__(1024) __half g_wt2[NS * 512 * 64];            // 2 MB
__device__ float g_bias[NS * (512 + 512 + 64)];

// Precomputed exp(log_std), sample-independent:
//  [0)      sig_w0 : 256*512
//  [131072) sig_w1 : 512*512
//  [393216) sig_w2 : 512*64
//  [425984) sig_b0 : 512, [426496) sig_b1 : 512, [427008) sig_b2 : 64
#define SIG_W0 0
#define SIG_W1 131072
#define SIG_W2 393216
#define SIG_B0 425984
#define SIG_B1 426496
#define SIG_B2 427008
#define SIG_TOTAL 427072
__device__ float g_sig[SIG_TOTAL];

// ---------------------------------------------------------------- helpers --
__device__ __forceinline__ float fast_tanh(float x) {
    float t = __expf(2.0f * x);
    return 1.0f - __fdividef(2.0f, t + 1.0f);
}

__device__ __forceinline__ void cp_async16(void* smem_dst, const void* gmem_src) {
    unsigned s = (unsigned)__cvta_generic_to_shared(smem_dst);
    asm volatile("cp.async.cg.shared.global [%0], [%1], 16;\n"
                 :: "r"(s), "l"(gmem_src));
}
__device__ __forceinline__ void cp_commit() {
    asm volatile("cp.async.commit_group;\n" ::: "memory");
}
template<int N>
__device__ __forceinline__ void cp_wait() {
    asm volatile("cp.async.wait_group %0;\n" :: "n"(N) : "memory");
}

__device__ __forceinline__ void mma_f16(
    float& d0, float& d1, float& d2, float& d3,
    uint32_t a0, uint32_t a1, uint32_t a2, uint32_t a3,
    uint32_t b0, uint32_t b1)
{
    asm volatile(
        "mma.sync.aligned.m16n8k16.row.col.f32.f16.f16.f32 "
        "{%0,%1,%2,%3}, {%4,%5,%6,%7}, {%8,%9}, {%0,%1,%2,%3};"
        : "+f"(d0), "+f"(d1), "+f"(d2), "+f"(d3)
        : "r"(a0), "r"(a1), "r"(a2), "r"(a3), "r"(b0), "r"(b1));
}

__device__ __forceinline__ void red_add_v2(float* addr, float v0, float v1) {
    asm volatile("red.global.add.v2.f32 [%0], {%1, %2};"
                 :: "l"(addr), "f"(v0), "f"(v1) : "memory");
}

__device__ __forceinline__ uint32_t h2u(__half2 h) {
    return *reinterpret_cast<uint32_t*>(&h);
}

// ------------------------------------------------------------ pack kernels --
// sig = exp(log_std) once (sample-independent).
__global__ __launch_bounds__(256) void sig_precompute_kernel(
    const float* __restrict__ wls0, const float* __restrict__ wls1,
    const float* __restrict__ wls2, const float* __restrict__ bls0,
    const float* __restrict__ bls1, const float* __restrict__ bls2)
{
    int i = blockIdx.x * 256 + threadIdx.x;
    if (i >= SIG_TOTAL) return;
    float v;
    if      (i < SIG_W1) v = wls0[i - SIG_W0];
    else if (i < SIG_W2) v = wls1[i - SIG_W1];
    else if (i < SIG_B0) v = wls2[i - SIG_W2];
    else if (i < SIG_B1) v = bls0[i - SIG_B0];
    else if (i < SIG_B2) v = bls1[i - SIG_B1];
    else                 v = bls2[i - SIG_B2];
    g_sig[i] = __expf(v);
}

// A fragment image: per (mtile[128 rows], kc16) block of 4KB:
//   [sub16 (8)][lane (32)][a0,a1,a2,a3 (16B)]
//   a0={A[g][2t4],A[g][2t4+1]} a1=rows+8  a2=cols+8  a3=both  (g=l>>2,t4=l&3)
__global__ __launch_bounds__(256) void pack_x_kernel(
    const float* __restrict__ x, __half* __restrict__ out)
{
    int t = blockIdx.x * 256 + threadIdx.x;      // 65536 fragments
    int lane = t & 31, sub16 = (t >> 5) & 7, kc = (t >> 8) & 15, mt = t >> 12;
    int g = lane >> 2, t4 = lane & 3;
    int m = mt * 128 + sub16 * 16 + g;
    int k = kc * 16 + 2 * t4;
    float2 v00 = *reinterpret_cast<const float2*>(&x[(size_t)m * 256 + k]);
    float2 v01 = *reinterpret_cast<const float2*>(&x[(size_t)m * 256 + k + 8]);
    float2 v10 = *reinterpret_cast<const float2*>(&x[(size_t)(m + 8) * 256 + k]);
    float2 v11 = *reinterpret_cast<const float2*>(&x[(size_t)(m + 8) * 256 + k + 8]);
    uint4 w;
    w.x = h2u(__float22half2_rn(v00));
    w.y = h2u(__float22half2_rn(v10));
    w.z = h2u(__float22half2_rn(v01));
    w.w = h2u(__float22half2_rn(v11));
    *reinterpret_cast<uint4*>(out + (size_t)t * 8) = w;
}

// B fragment image, PAIR-PACKED: per (ntile[BN], kc16) block of BN*16 halves:
//   [n8pair (BN/16)][lane (32)][even.b0, even.b1, odd.b0, odd.b1]  (16B/lane)
//   b0={W[2t4][n],W[2t4+1][n]}  b1={W[2t4+8][n],W[2t4+9][n]}   n = n8*8+g
// W = z * sig + m, with sig PRECOMPUTED (no expf here).
__global__ __launch_bounds__(256) void pack_w_kernel(
    const float* __restrict__ zw, const float* __restrict__ sigw,
    const float* __restrict__ wm, __half* __restrict__ out,
    int K, int N, int BN)
{
    __shared__ float tile[32][33];
    const int n0 = blockIdx.x * 32, k0 = blockIdx.y * 32, s = blockIdx.z;
    const int t = threadIdx.x;
    {
        int kk = t >> 3, nn4 = (t & 7) * 4;
        size_t io = (size_t)(k0 + kk) * N + n0 + nn4;
        float4 z = *reinterpret_cast<const float4*>(zw + (size_t)s * K * N + io);
        float4 sg = *reinterpret_cast<const float4*>(sigw + io);
        float4 m = *reinterpret_cast<const float4*>(wm + io);
        tile[kk][nn4 + 0] = fmaf(z.x, sg.x, m.x);
        tile[kk][nn4 + 1] = fmaf(z.y, sg.y, m.y);
        tile[kk][nn4 + 2] = fmaf(z.z, sg.z, m.z);
        tile[kk][nn4 + 3] = fmaf(z.w, sg.w, m.w);
    }
    __syncthreads();
    {
        int kc_loc = t >> 7, n8_loc = (t >> 5) & 3, lane = t & 31;
        int g = lane >> 2, t4 = lane & 3;
        int kr = kc_loc * 16 + 2 * t4;
        int nc = n8_loc * 8 + g;
        float b00 = tile[kr][nc],     b01 = tile[kr + 1][nc];
        float b10 = tile[kr + 8][nc], b11 = tile[kr + 9][nc];
        uint2 w;
        w.x = h2u(__float22half2_rn(make_float2(b00, b01)));
        w.y = h2u(__float22half2_rn(make_float2(b10, b11)));
        int n_g = n0 + n8_loc * 8;
        int nt = n_g / BN, n8b = (n_g % BN) >> 3;
        int kc_g = (k0 >> 4) + kc_loc;
        size_t blk = ((size_t)(s * (N / BN) + nt) * (K >> 4) + kc_g)
                     * (size_t)(BN * 16);
        size_t off = ((size_t)((n8b >> 1) * 32 + lane)) * 8 + (n8b & 1) * 4;
        *reinterpret_cast<uint2*>(out + blk + off) = w;
    }
}

__global__ __launch_bounds__(256) void pack_bias_kernel(
    const float* __restrict__ zb0, const float* __restrict__ bm0,
    const float* __restrict__ zb1, const float* __restrict__ bm1,
    const float* __restrict__ zb2, const float* __restrict__ bm2)
{
    int i = blockIdx.x * 256 + threadIdx.x;
    if (i >= NS * 1088) return;
    float v;
    if (i < 16384)      { int n = i & 511;                v = fmaf(zb0[i], g_sig[SIG_B0 + n], bm0[n]); }
    else if (i < 32768) { int j = i - 16384, n = j & 511; v = fmaf(zb1[j], g_sig[SIG_B1 + n], bm1[n]); }
    else                { int j = i - 32768, n = j & 63;  v = fmaf(zb2[j], g_sig[SIG_B2 + n], bm2[n]); }
    g_bias[i] = v;
}

// Initialize d_out with the L2 bias (split-K partials RED on top of it).
__global__ __launch_bounds__(256) void out_init_kernel(
    float* __restrict__ out, const float* __restrict__ bias2)
{
    int i = blockIdx.x * 256 + threadIdx.x;       // NS*BATCH*64 = 4194304
    int s = i >> 17, n = i & 63;
    out[i] = __ldg(&bias2[s * 64 + n]);
}

// ------------------------------------------------------------------- GEMM --
// D[s] (128 x BN) = A(128,K) @ W(K,BN) + bias, opt tanh.
// Stage = 64 K (four kc16 blocks), 3-stage cp.async pipeline.
// KC = number of kc16 blocks (stages = KC/4).
// FUSE: after staging the (tanh'd) tile in smem, run the L2 mini-GEMM
//   out[s][mrows][0:64] += stg(128 x 128) @ W2[nt*128 : nt*128+128, 0:64]
// with red.v2.f32 split-K over the 4 nt CTAs.
template<int BN, int WM, int WN, bool TANH, bool PACKOUT, bool FUSE>
__global__ __launch_bounds__(256, 2) void gemm_f16k(
    const __half* __restrict__ Apk, size_t aStr,
    const __half* __restrict__ Bpk, size_t bStr,
    const float* __restrict__ bias, int bStride,
    float* __restrict__ outPlain, __half* __restrict__ outPk,
    const __half* __restrict__ B2pk, float* __restrict__ outFused,
    int KC, int KCnext)
{
    constexpr int MI = 8 / WM;            // m16 tiles per warp
    constexpr int NI = (BN / WN) / 8;     // n8 tiles per warp
    constexpr int ST_A = 128 * 64;        // halfs per A stage (16KB)
    constexpr int ST_B = BN * 64;         // halfs per B stage
    constexpr int ST   = ST_A + ST_B;
    constexpr int A16  = 128 * 16;        // halfs per A kc16 block
    constexpr int B16  = BN * 16;
    extern __shared__ __align__(16) __half smem[];

    const int tid = threadIdx.x, wid = tid >> 5, lane = tid & 31;
    const int g = lane >> 2, t4 = lane & 3;
    const int s = blockIdx.z, nt = blockIdx.x, mt = blockIdx.y;
    const int wm16 = (wid / WN) * MI;
    const int wn8  = (wid % WN) * NI;

    const __half* Ab = Apk + (size_t)s * aStr + (size_t)mt * KC * A16;
    const __half* Bb = Bpk + (size_t)s * bStr + (size_t)nt * KC * B16;

    float acc[MI][NI][4];
    #pragma unroll
    for (int i = 0; i < MI; i++)
        #pragma unroll
        for (int j = 0; j < NI; j++)
            #pragma unroll
            for (int r = 0; r < 4; r++) acc[i][j][r] = 0.0f;

    const int KS = KC >> 2;               // stages (K=64 each)

    auto issue = [&](int ks, int st) {
        __half* As = smem + st * ST;
        __half* Bs = As + ST_A;
        #pragma unroll
        for (int i = 0; i < ST_A / (256 * 8); i++)
            cp_async16(As + (tid + i * 256) * 8,
                       Ab + (size_t)ks * ST_A + (tid + i * 256) * 8);
        #pragma unroll
        for (int i = 0; i < ST_B / (256 * 8); i++)
            cp_async16(Bs + (tid + i * 256) * 8,
                       Bb + (size_t)ks * ST_B + (tid + i * 256) * 8);
        cp_commit();
    };

    issue(0, 0);
    if (KS > 1) issue(1, 1);

    for (int ks = 0; ks < KS; ks++) {
        if (ks >= KS - 2) cp_wait<0>(); else cp_wait<1>();
        __syncthreads();
        if (ks + 2 < KS) issue(ks + 2, (ks + 2) % 3);

        const __half* Asb = smem + (ks % 3) * ST;
        #pragma unroll
        for (int kb = 0; kb < 4; kb++) {
            const __half* As = Asb + kb * A16;
            const __half* Bs = Asb + ST_A + kb * B16;

            uint32_t aR[MI][4];
            #pragma unroll
            for (int mi = 0; mi < MI; mi++) {
                const uint4 v = *reinterpret_cast<const uint4*>(
                    As + ((wm16 + mi) * 32 + lane) * 8);
                aR[mi][0] = v.x; aR[mi][1] = v.y; aR[mi][2] = v.z; aR[mi][3] = v.w;
            }
            uint32_t bR[NI][2];
            #pragma unroll
            for (int p = 0; p < NI / 2; p++) {
                const uint4 v = *reinterpret_cast<const uint4*>(
                    Bs + (((wn8 >> 1) + p) * 32 + lane) * 8);
                bR[2 * p][0] = v.x; bR[2 * p][1] = v.y;
                bR[2 * p + 1][0] = v.z; bR[2 * p + 1][1] = v.w;
            }
            #pragma unroll
            for (int mi = 0; mi < MI; mi++)
                #pragma unroll
                for (int ni = 0; ni < NI; ni++)
                    mma_f16(acc[mi][ni][0], acc[mi][ni][1],
                            acc[mi][ni][2], acc[mi][ni][3],
                            aR[mi][0], aR[mi][1], aR[mi][2], aR[mi][3],
                            bR[ni][0], bR[ni][1]);
        }
    }
    __syncthreads();

    // ---- epilogue
    if (!PACKOUT && !FUSE) {
        #pragma unroll
        for (int ni = 0; ni < NI; ni++) {
            int c = wn8 * 8 + ni * 8 + 2 * t4;
            float b0 = __ldg(&bias[(size_t)s * bStride + nt * BN + c]);
            float b1 = __ldg(&bias[(size_t)s * bStride + nt * BN + c + 1]);
            #pragma unroll
            for (int mi = 0; mi < MI; mi++) {
                int r = (wm16 + mi) * 16 + g;
                float v0 = acc[mi][ni][0] + b0, v1 = acc[mi][ni][1] + b1;
                float v2 = acc[mi][ni][2] + b0, v3 = acc[mi][ni][3] + b1;
                if (TANH) { v0 = fast_tanh(v0); v1 = fast_tanh(v1);
                            v2 = fast_tanh(v2); v3 = fast_tanh(v3); }
                size_t base = ((size_t)s * BATCH + mt * 128) * BN;
                *reinterpret_cast<float2*>(outPlain + base + (size_t)r * BN + c) =
                    make_float2(v0, v1);
                *reinterpret_cast<float2*>(outPlain + base + (size_t)(r + 8) * BN + c) =
                    make_float2(v2, v3);
            }
        }
        return;
    }

    // staged epilogue: phase 1 -> smem fp32 [128][BN+4] with bias + tanh
    float* stg = reinterpret_cast<float*>(smem);
    constexpr int SSTR = BN + 4;
    #pragma unroll
    for (int ni = 0; ni < NI; ni++) {
        int c = wn8 * 8 + ni * 8 + 2 * t4;
        float b0 = __ldg(&bias[(size_t)s * bStride + nt * BN + c]);
        float b1 = __ldg(&bias[(size_t)s * bStride + nt * BN + c + 1]);
        #pragma unroll
        for (int mi = 0; mi < MI; mi++) {
            int r = (wm16 + mi) * 16 + g;
            float v0 = acc[mi][ni][0] + b0, v1 = acc[mi][ni][1] + b1;
            float v2 = acc[mi][ni][2] + b0, v3 = acc[mi][ni][3] + b1;
            if (TANH) { v0 = fast_tanh(v0); v1 = fast_tanh(v1);
                        v2 = fast_tanh(v2); v3 = fast_tanh(v3); }
            *reinterpret_cast<float2*>(&stg[r * SSTR + c]) = make_float2(v0, v1);
            *reinterpret_cast<float2*>(&stg[(r + 8) * SSTR + c]) = make_float2(v2, v3);
        }
    }
    __syncthreads();

    if (PACKOUT) {
        // phase 2: write next layer's fragment-A blocks, coalesced 16B/thread
        #pragma unroll
        for (int ff = 0; ff < BN / 16; ff++) {
            int sub16 = tid >> 5;
            int r0 = sub16 * 16 + g;
            int c0 = ff * 16 + 2 * t4;
            float2 p00 = *reinterpret_cast<const float2*>(&stg[r0 * SSTR + c0]);
            float2 p10 = *reinterpret_cast<const float2*>(&stg[(r0 + 8) * SSTR + c0]);
            float2 p01 = *reinterpret_cast<const float2*>(&stg[r0 * SSTR + c0 + 8]);
            float2 p11 = *reinterpret_cast<const float2*>(&stg[(r0 + 8) * SSTR + c0 + 8]);
            uint4 w;
            w.x = h2u(__float22half2_rn(p00));
            w.y = h2u(__float22half2_rn(p10));
            w.z = h2u(__float22half2_rn(p01));
            w.w = h2u(__float22half2_rn(p11));
            size_t blk = ((size_t)(s * (BATCH / 128) + mt) * KCnext
                          + nt * (BN / 16) + ff) * (size_t)(128 * 16);
            *reinterpret_cast<uint4*>(outPk + blk + (size_t)tid * 8) = w;
        }
    }

    if (FUSE) {
        // mini-GEMM: out(128 x 64) += stg(128 x 128) @ W2[nt*128 .. , 0:64]
        // 8 warps over M (wid = m16 index). B2 kc blocks nt*8 .. nt*8+7,
        // pair-packed layout (BN2=64 -> 4 pairs), 1024 halves per block.
        const __half* B2 = B2pk + (size_t)s * (512 * 64)
                         + (size_t)(nt * 8) * 1024;
        float a2cc[8][4];
        #pragma unroll
        for (int ni = 0; ni < 8; ni++)
            #pragma unroll
            for (int r = 0; r < 4; r++) a2cc[ni][r] = 0.0f;

        #pragma unroll
        for (int kb = 0; kb < 8; kb++) {
            int r0 = wid * 16 + g;
            int c0 = kb * 16 + 2 * t4;
            float2 p00 = *reinterpret_cast<const float2*>(&stg[r0 * SSTR + c0]);
            float2 p10 = *reinterpret_cast<const float2*>(&stg[(r0 + 8) * SSTR + c0]);
            float2 p01 = *reinterpret_cast<const float2*>(&stg[r0 * SSTR + c0 + 8]);
            float2 p11 = *reinterpret_cast<const float2*>(&stg[(r0 + 8) * SSTR + c0 + 8]);
            uint32_t a0 = h2u(__float22half2_rn(p00));
            uint32_t a1 = h2u(__float22half2_rn(p10));
            uint32_t a2 = h2u(__float22half2_rn(p01));
            uint32_t a3 = h2u(__float22half2_rn(p11));
            uint32_t b2r[8][2];
            #pragma unroll
            for (int p = 0; p < 4; p++) {
                const uint4 v = __ldg(reinterpret_cast<const uint4*>(
                    B2 + (size_t)kb * 1024 + (p * 32 + lane) * 8));
                b2r[2 * p][0] = v.x; b2r[2 * p][1] = v.y;
                b2r[2 * p + 1][0] = v.z; b2r[2 * p + 1][1] = v.w;
            }
            #pragma unroll
            for (int ni = 0; ni < 8; ni++)
                mma_f16(a2cc[ni][0], a2cc[ni][1], a2cc[ni][2], a2cc[ni][3],
                        a0, a1, a2, a3, b2r[ni][0], b2r[ni][1]);
        }
        float* o = outFused + ((size_t)s * BATCH + mt * 128 + wid * 16) * 64;
        #pragma unroll
        for (int ni = 0; ni < 8; ni++) {
            int c = ni * 8 + 2 * t4;
            red_add_v2(&o[g * 64 + c],       a2cc[ni][0], a2cc[ni][1]);
            red_add_v2(&o[(g + 8) * 64 + c], a2cc[ni][2], a2cc[ni][3]);
        }
    }
}

// ------------------------------------------------------------------- host --
extern "C" void kernel_launch(void* const* d_in, const int* in_sizes, int n_in,
                              void* d_out, int out_size)
{
    const float* x    = (const float*)d_in[0];
    const float* wm0  = (const float*)d_in[1];
    const float* wls0 = (const float*)d_in[2];
    const float* bm0  = (const float*)d_in[3];
    const float* bls0 = (const float*)d_in[4];
    const float* zw0  = (const float*)d_in[5];
    const float* zb0  = (const float*)d_in[6];
    const float* wm1  = (const float*)d_in[7];
    const float* wls1 = (const float*)d_in[8];
    const float* bm1  = (const float*)d_in[9];
    const float* bls1 = (const float*)d_in[10];
    const float* zw1  = (const float*)d_in[11];
    const float* zb1  = (const float*)d_in[12];
    const float* wm2  = (const float*)d_in[13];
    const float* wls2 = (const float*)d_in[14];
    const float* bm2  = (const float*)d_in[15];
    const float* bls2 = (const float*)d_in[16];
    const float* zw2  = (const float*)d_in[17];
    const float* zb2  = (const float*)d_in[18];

    __half *h0, *xpk, *wt0, *wt1, *wt2;
    float *bias, *sig;
    cudaGetSymbolAddress((void**)&h0,  g_h0);
    cudaGetSymbolAddress((void**)&xpk, g_xpk);
    cudaGetSymbolAddress((void**)&wt0, g_wt0);
    cudaGetSymbolAddress((void**)&wt1, g_wt1);
    cudaGetSymbolAddress((void**)&wt2, g_wt2);
    cudaGetSymbolAddress((void**)&bias, g_bias);
    cudaGetSymbolAddress((void**)&sig,  g_sig);

    // 3 stages x (128+128)*64 halfs = 96KB; epilogue staging union 67.6KB
    const int SMEM_BIG = 3 * (128 * 64 + 128 * 64) * 2;    // 98304
    cudaFuncSetAttribute(gemm_f16k<128, 2, 4, true, true,  false>,
                         cudaFuncAttributeMaxDynamicSharedMemorySize, SMEM_BIG);
    cudaFuncSetAttribute(gemm_f16k<128, 2, 4, true, false, true >,
                         cudaFuncAttributeMaxDynamicSharedMemorySize, SMEM_BIG);

    // ---- sig = exp(log_std) ONCE (sample-independent)
    sig_precompute_kernel<<<(SIG_TOTAL + 255) / 256, 256>>>(
        wls0, wls1, wls2, bls0, bls1, bls2);

    // ---- pack (no expf anywhere below)
    pack_x_kernel<<<256, 256>>>(x, xpk);
    pack_w_kernel<<<dim3(512 / 32, 256 / 32, NS), 256>>>(zw0, sig + SIG_W0, wm0, wt0, 256, 512, 128);
    pack_w_kernel<<<dim3(512 / 32, 512 / 32, NS), 256>>>(zw1, sig + SIG_W1, wm1, wt1, 512, 512, 128);
    pack_w_kernel<<<dim3(64 / 32, 512 / 32, NS), 256>>>(zw2, sig + SIG_W2, wm2, wt2, 512, 64, 64);
    pack_bias_kernel<<<(NS * 1088 + 255) / 256, 256>>>(zb0, bm0, zb1, bm1, zb2, bm2);

    // ---- init out with L2 bias (split-K partials RED on top)
    out_init_kernel<<<(NS * BATCH * 64) / 256, 256>>>((float*)d_out, bias + 32768);

    // ---- layer 0: (2048,256)@(256,512) -> tanh -> h0 (frag-packed)
    gemm_f16k<128, 2, 4, true, true, false><<<dim3(4, 16, NS), 256, SMEM_BIG>>>(
        xpk, 0, wt0, (size_t)256 * 512,
        bias, 512, nullptr, h0, nullptr, nullptr, /*KC=*/16, /*KCnext=*/32);

    // ---- layer 1 + fused layer 2:
    //      h1 = tanh((2048,512)@(512,512)+b1) staged in smem;
    //      out += h1_tile @ W2-slice (split-K over nt, red.v2).
    gemm_f16k<128, 2, 4, true, false, true><<<dim3(4, 16, NS), 256, SMEM_BIG>>>(
        h0, (size_t)BATCH * 512, wt1, (size_t)512 * 512,
        bias + 16384, 512, nullptr, nullptr, wt2, (float*)d_out,
        /*KC=*/32, /*KCnext=*/0);
}

// round 14
// speedup vs baseline: 1.0202x; 1.0202x over previous
#include <cuda_runtime.h>
#include <cuda_fp16.h>
#include <cstdint>

// ---------------------------------------------------------------------------
// BayesianNN (sm_103 target, legacy mma path):
// out[s] = L2( tanh(L1( tanh(L0(x)) )) ),  Li: h @ (z_w*e^ls + m) + bias
// S=32, B=2048, dims 256 -> 512 -> 512 -> 64, fp32 in/out.
//
// Round 14: graph fork/join — wt1/wt2 packing runs on a side stream
// CONCURRENTLY with the L0 GEMM (they are only needed by L1). Everything
// else unchanged from round 13 (fp16 fragment-packed GEMMs, K=64 stages,
// fused L2 with red.v2.f32 split-K, sig precompute).
// ---------------------------------------------------------------------------

#define NS 32
#define BATCH 2048

__device__ __align__(1024) __half g_h0[(size_t)NS * BATCH * 512];  // 64 MB
__device__ __align__(1024) __half g_xpk[BATCH * 256];              // 1 MB
__device__ __align__(1024) __half g_wt0[NS * 256 * 512];           // 8 MB
__device__ __align__(1024) __half g_wt1[NS * 512 * 512];           // 16 MB
__device__ __align__(1024) __half g_wt2[NS * 512 * 64];            // 2 MB
__device__ float g_bias[NS * (512 + 512 + 64)];

#define SIG_W0 0
#define SIG_W1 131072
#define SIG_W2 393216
#define SIG_B0 425984
#define SIG_B1 426496
#define SIG_B2 427008
#define SIG_TOTAL 427072
__device__ float g_sig[SIG_TOTAL];

// ---------------------------------------------------------------- helpers --
__device__ __forceinline__ float fast_tanh(float x) {
    float t = __expf(2.0f * x);
    return 1.0f - __fdividef(2.0f, t + 1.0f);
}

__device__ __forceinline__ void cp_async16(void* smem_dst, const void* gmem_src) {
    unsigned s = (unsigned)__cvta_generic_to_shared(smem_dst);
    asm volatile("cp.async.cg.shared.global [%0], [%1], 16;\n"
                 :: "r"(s), "l"(gmem_src));
}
__device__ __forceinline__ void cp_commit() {
    asm volatile("cp.async.commit_group;\n" ::: "memory");
}
template<int N>
__device__ __forceinline__ void cp_wait() {
    asm volatile("cp.async.wait_group %0;\n" :: "n"(N) : "memory");
}

__device__ __forceinline__ void mma_f16(
    float& d0, float& d1, float& d2, float& d3,
    uint32_t a0, uint32_t a1, uint32_t a2, uint32_t a3,
    uint32_t b0, uint32_t b1)
{
    asm volatile(
        "mma.sync.aligned.m16n8k16.row.col.f32.f16.f16.f32 "
        "{%0,%1,%2,%3}, {%4,%5,%6,%7}, {%8,%9}, {%0,%1,%2,%3};"
        : "+f"(d0), "+f"(d1), "+f"(d2), "+f"(d3)
        : "r"(a0), "r"(a1), "r"(a2), "r"(a3), "r"(b0), "r"(b1));
}

__device__ __forceinline__ void red_add_v2(float* addr, float v0, float v1) {
    asm volatile("red.global.add.v2.f32 [%0], {%1, %2};"
                 :: "l"(addr), "f"(v0), "f"(v1) : "memory");
}

__device__ __forceinline__ uint32_t h2u(__half2 h) {
    return *reinterpret_cast<uint32_t*>(&h);
}

// ------------------------------------------------------------ pack kernels --
__global__ __launch_bounds__(256) void sig_precompute_kernel(
    const float* __restrict__ wls0, const float* __restrict__ wls1,
    const float* __restrict__ wls2, const float* __restrict__ bls0,
    const float* __restrict__ bls1, const float* __restrict__ bls2)
{
    int i = blockIdx.x * 256 + threadIdx.x;
    if (i >= SIG_TOTAL) return;
    float v;
    if      (i < SIG_W1) v = wls0[i - SIG_W0];
    else if (i < SIG_W2) v = wls1[i - SIG_W1];
    else if (i < SIG_B0) v = wls2[i - SIG_W2];
    else if (i < SIG_B1) v = bls0[i - SIG_B0];
    else if (i < SIG_B2) v = bls1[i - SIG_B1];
    else                 v = bls2[i - SIG_B2];
    g_sig[i] = __expf(v);
}

// A fragment image: per (mtile[128 rows], kc16) block of 4KB:
//   [sub16 (8)][lane (32)][a0,a1,a2,a3 (16B)]
__global__ __launch_bounds__(256) void pack_x_kernel(
    const float* __restrict__ x, __half* __restrict__ out)
{
    int t = blockIdx.x * 256 + threadIdx.x;      // 65536 fragments
    int lane = t & 31, sub16 = (t >> 5) & 7, kc = (t >> 8) & 15, mt = t >> 12;
    int g = lane >> 2, t4 = lane & 3;
    int m = mt * 128 + sub16 * 16 + g;
    int k = kc * 16 + 2 * t4;
    float2 v00 = *reinterpret_cast<const float2*>(&x[(size_t)m * 256 + k]);
    float2 v01 = *reinterpret_cast<const float2*>(&x[(size_t)m * 256 + k + 8]);
    float2 v10 = *reinterpret_cast<const float2*>(&x[(size_t)(m + 8) * 256 + k]);
    float2 v11 = *reinterpret_cast<const float2*>(&x[(size_t)(m + 8) * 256 + k + 8]);
    uint4 w;
    w.x = h2u(__float22half2_rn(v00));
    w.y = h2u(__float22half2_rn(v10));
    w.z = h2u(__float22half2_rn(v01));
    w.w = h2u(__float22half2_rn(v11));
    *reinterpret_cast<uint4*>(out + (size_t)t * 8) = w;
}

// B fragment image, PAIR-PACKED: per (ntile[BN], kc16) block of BN*16 halves.
__global__ __launch_bounds__(256) void pack_w_kernel(
    const float* __restrict__ zw, const float* __restrict__ sigw,
    const float* __restrict__ wm, __half* __restrict__ out,
    int K, int N, int BN)
{
    __shared__ float tile[32][33];
    const int n0 = blockIdx.x * 32, k0 = blockIdx.y * 32, s = blockIdx.z;
    const int t = threadIdx.x;
    {
        int kk = t >> 3, nn4 = (t & 7) * 4;
        size_t io = (size_t)(k0 + kk) * N + n0 + nn4;
        float4 z = *reinterpret_cast<const float4*>(zw + (size_t)s * K * N + io);
        float4 sg = *reinterpret_cast<const float4*>(sigw + io);
        float4 m = *reinterpret_cast<const float4*>(wm + io);
        tile[kk][nn4 + 0] = fmaf(z.x, sg.x, m.x);
        tile[kk][nn4 + 1] = fmaf(z.y, sg.y, m.y);
        tile[kk][nn4 + 2] = fmaf(z.z, sg.z, m.z);
        tile[kk][nn4 + 3] = fmaf(z.w, sg.w, m.w);
    }
    __syncthreads();
    {
        int kc_loc = t >> 7, n8_loc = (t >> 5) & 3, lane = t & 31;
        int g = lane >> 2, t4 = lane & 3;
        int kr = kc_loc * 16 + 2 * t4;
        int nc = n8_loc * 8 + g;
        float b00 = tile[kr][nc],     b01 = tile[kr + 1][nc];
        float b10 = tile[kr + 8][nc], b11 = tile[kr + 9][nc];
        uint2 w;
        w.x = h2u(__float22half2_rn(make_float2(b00, b01)));
        w.y = h2u(__float22half2_rn(make_float2(b10, b11)));
        int n_g = n0 + n8_loc * 8;
        int nt = n_g / BN, n8b = (n_g % BN) >> 3;
        int kc_g = (k0 >> 4) + kc_loc;
        size_t blk = ((size_t)(s * (N / BN) + nt) * (K >> 4) + kc_g)
                     * (size_t)(BN * 16);
        size_t off = ((size_t)((n8b >> 1) * 32 + lane)) * 8 + (n8b & 1) * 4;
        *reinterpret_cast<uint2*>(out + blk + off) = w;
    }
}

__global__ __launch_bounds__(256) void pack_bias_kernel(
    const float* __restrict__ zb0, const float* __restrict__ bm0,
    const float* __restrict__ zb1, const float* __restrict__ bm1,
    const float* __restrict__ zb2, const float* __restrict__ bm2)
{
    int i = blockIdx.x * 256 + threadIdx.x;
    if (i >= NS * 1088) return;
    float v;
    if (i < 16384)      { int n = i & 511;                v = fmaf(zb0[i], g_sig[SIG_B0 + n], bm0[n]); }
    else if (i < 32768) { int j = i - 16384, n = j & 511; v = fmaf(zb1[j], g_sig[SIG_B1 + n], bm1[n]); }
    else                { int j = i - 32768, n = j & 63;  v = fmaf(zb2[j], g_sig[SIG_B2 + n], bm2[n]); }
    g_bias[i] = v;
}

// Initialize d_out with the L2 bias (split-K partials RED on top of it).
__global__ __launch_bounds__(256) void out_init_kernel(
    float* __restrict__ out, const float* __restrict__ bias2)
{
    int i = blockIdx.x * 256 + threadIdx.x;       // NS*BATCH*64 = 4194304
    int s = i >> 17, n = i & 63;
    out[i] = __ldg(&bias2[s * 64 + n]);
}

// ------------------------------------------------------------------- GEMM --
// D[s] (128 x BN) = A(128,K) @ W(K,BN) + bias, opt tanh.
// Stage = 64 K (four kc16 blocks), 3-stage cp.async pipeline.
template<int BN, int WM, int WN, bool TANH, bool PACKOUT, bool FUSE>
__global__ __launch_bounds__(256, 2) void gemm_f16k(
    const __half* __restrict__ Apk, size_t aStr,
    const __half* __restrict__ Bpk, size_t bStr,
    const float* __restrict__ bias, int bStride,
    float* __restrict__ outPlain, __half* __restrict__ outPk,
    const __half* __restrict__ B2pk, float* __restrict__ outFused,
    int KC, int KCnext)
{
    constexpr int MI = 8 / WM;
    constexpr int NI = (BN / WN) / 8;
    constexpr int ST_A = 128 * 64;        // halfs per A stage (16KB)
    constexpr int ST_B = BN * 64;
    constexpr int ST   = ST_A + ST_B;
    constexpr int A16  = 128 * 16;
    constexpr int B16  = BN * 16;
    extern __shared__ __align__(16) __half smem[];

    const int tid = threadIdx.x, wid = tid >> 5, lane = tid & 31;
    const int g = lane >> 2, t4 = lane & 3;
    const int s = blockIdx.z, nt = blockIdx.x, mt = blockIdx.y;
    const int wm16 = (wid / WN) * MI;
    const int wn8  = (wid % WN) * NI;

    const __half* Ab = Apk + (size_t)s * aStr + (size_t)mt * KC * A16;
    const __half* Bb = Bpk + (size_t)s * bStr + (size_t)nt * KC * B16;

    float acc[MI][NI][4];
    #pragma unroll
    for (int i = 0; i < MI; i++)
        #pragma unroll
        for (int j = 0; j < NI; j++)
            #pragma unroll
            for (int r = 0; r < 4; r++) acc[i][j][r] = 0.0f;

    const int KS = KC >> 2;

    auto issue = [&](int ks, int st) {
        __half* As = smem + st * ST;
        __half* Bs = As + ST_A;
        #pragma unroll
        for (int i = 0; i < ST_A / (256 * 8); i++)
            cp_async16(As + (tid + i * 256) * 8,
                       Ab + (size_t)ks * ST_A + (tid + i * 256) * 8);
        #pragma unroll
        for (int i = 0; i < ST_B / (256 * 8); i++)
            cp_async16(Bs + (tid + i * 256) * 8,
                       Bb + (size_t)ks * ST_B + (tid + i * 256) * 8);
        cp_commit();
    };

    issue(0, 0);
    if (KS > 1) issue(1, 1);

    for (int ks = 0; ks < KS; ks++) {
        if (ks >= KS - 2) cp_wait<0>(); else cp_wait<1>();
        __syncthreads();
        if (ks + 2 < KS) issue(ks + 2, (ks + 2) % 3);

        const __half* Asb = smem + (ks % 3) * ST;
        #pragma unroll
        for (int kb = 0; kb < 4; kb++) {
            const __half* As = Asb + kb * A16;
            const __half* Bs = Asb + ST_A + kb * B16;

            uint32_t aR[MI][4];
            #pragma unroll
            for (int mi = 0; mi < MI; mi++) {
                const uint4 v = *reinterpret_cast<const uint4*>(
                    As + ((wm16 + mi) * 32 + lane) * 8);
                aR[mi][0] = v.x; aR[mi][1] = v.y; aR[mi][2] = v.z; aR[mi][3] = v.w;
            }
            uint32_t bR[NI][2];
            #pragma unroll
            for (int p = 0; p < NI / 2; p++) {
                const uint4 v = *reinterpret_cast<const uint4*>(
                    Bs + (((wn8 >> 1) + p) * 32 + lane) * 8);
                bR[2 * p][0] = v.x; bR[2 * p][1] = v.y;
                bR[2 * p + 1][0] = v.z; bR[2 * p + 1][1] = v.w;
            }
            #pragma unroll
            for (int mi = 0; mi < MI; mi++)
                #pragma unroll
                for (int ni = 0; ni < NI; ni++)
                    mma_f16(acc[mi][ni][0], acc[mi][ni][1],
                            acc[mi][ni][2], acc[mi][ni][3],
                            aR[mi][0], aR[mi][1], aR[mi][2], aR[mi][3],
                            bR[ni][0], bR[ni][1]);
        }
    }
    __syncthreads();

    // ---- epilogue
    if (!PACKOUT && !FUSE) {
        #pragma unroll
        for (int ni = 0; ni < NI; ni++) {
            int c = wn8 * 8 + ni * 8 + 2 * t4;
            float b0 = __ldg(&bias[(size_t)s * bStride + nt * BN + c]);
            float b1 = __ldg(&bias[(size_t)s * bStride + nt * BN + c + 1]);
            #pragma unroll
            for (int mi = 0; mi < MI; mi++) {
                int r = (wm16 + mi) * 16 + g;
                float v0 = acc[mi][ni][0] + b0, v1 = acc[mi][ni][1] + b1;
                float v2 = acc[mi][ni][2] + b0, v3 = acc[mi][ni][3] + b1;
                if (TANH) { v0 = fast_tanh(v0); v1 = fast_tanh(v1);
                            v2 = fast_tanh(v2); v3 = fast_tanh(v3); }
                size_t base = ((size_t)s * BATCH + mt * 128) * BN;
                *reinterpret_cast<float2*>(outPlain + base + (size_t)r * BN + c) =
                    make_float2(v0, v1);
                *reinterpret_cast<float2*>(outPlain + base + (size_t)(r + 8) * BN + c) =
                    make_float2(v2, v3);
            }
        }
        return;
    }

    // staged epilogue: phase 1 -> smem fp32 [128][BN+4] with bias + tanh
    float* stg = reinterpret_cast<float*>(smem);
    constexpr int SSTR = BN + 4;
    #pragma unroll
    for (int ni = 0; ni < NI; ni++) {
        int c = wn8 * 8 + ni * 8 + 2 * t4;
        float b0 = __ldg(&bias[(size_t)s * bStride + nt * BN + c]);
        float b1 = __ldg(&bias[(size_t)s * bStride + nt * BN + c + 1]);
        #pragma unroll
        for (int mi = 0; mi < MI; mi++) {
            int r = (wm16 + mi) * 16 + g;
            float v0 = acc[mi][ni][0] + b0, v1 = acc[mi][ni][1] + b1;
            float v2 = acc[mi][ni][2] + b0, v3 = acc[mi][ni][3] + b1;
            if (TANH) { v0 = fast_tanh(v0); v1 = fast_tanh(v1);
                        v2 = fast_tanh(v2); v3 = fast_tanh(v3); }
            *reinterpret_cast<float2*>(&stg[r * SSTR + c]) = make_float2(v0, v1);
            *reinterpret_cast<float2*>(&stg[(r + 8) * SSTR + c]) = make_float2(v2, v3);
        }
    }
    __syncthreads();

    if (PACKOUT) {
        #pragma unroll
        for (int ff = 0; ff < BN / 16; ff++) {
            int sub16 = tid >> 5;
            int r0 = sub16 * 16 + g;
            int c0 = ff * 16 + 2 * t4;
            float2 p00 = *reinterpret_cast<const float2*>(&stg[r0 * SSTR + c0]);
            float2 p10 = *reinterpret_cast<const float2*>(&stg[(r0 + 8) * SSTR + c0]);
            float2 p01 = *reinterpret_cast<const float2*>(&stg[r0 * SSTR + c0 + 8]);
            float2 p11 = *reinterpret_cast<const float2*>(&stg[(r0 + 8) * SSTR + c0 + 8]);
            uint4 w;
            w.x = h2u(__float22half2_rn(p00));
            w.y = h2u(__float22half2_rn(p10));
            w.z = h2u(__float22half2_rn(p01));
            w.w = h2u(__float22half2_rn(p11));
            size_t blk = ((size_t)(s * (BATCH / 128) + mt) * KCnext
                          + nt * (BN / 16) + ff) * (size_t)(128 * 16);
            *reinterpret_cast<uint4*>(outPk + blk + (size_t)tid * 8) = w;
        }
    }

    if (FUSE) {
        const __half* B2 = B2pk + (size_t)s * (512 * 64)
                         + (size_t)(nt * 8) * 1024;
        float a2cc[8][4];
        #pragma unroll
        for (int ni = 0; ni < 8; ni++)
            #pragma unroll
            for (int r = 0; r < 4; r++) a2cc[ni][r] = 0.0f;

        #pragma unroll
        for (int kb = 0; kb < 8; kb++) {
            int r0 = wid * 16 + g;
            int c0 = kb * 16 + 2 * t4;
            float2 p00 = *reinterpret_cast<const float2*>(&stg[r0 * SSTR + c0]);
            float2 p10 = *reinterpret_cast<const float2*>(&stg[(r0 + 8) * SSTR + c0]);
            float2 p01 = *reinterpret_cast<const float2*>(&stg[r0 * SSTR + c0 + 8]);
            float2 p11 = *reinterpret_cast<const float2*>(&stg[(r0 + 8) * SSTR + c0 + 8]);
            uint32_t a0 = h2u(__float22half2_rn(p00));
            uint32_t a1 = h2u(__float22half2_rn(p10));
            uint32_t a2 = h2u(__float22half2_rn(p01));
            uint32_t a3 = h2u(__float22half2_rn(p11));
            uint32_t b2r[8][2];
            #pragma unroll
            for (int p = 0; p < 4; p++) {
                const uint4 v = __ldg(reinterpret_cast<const uint4*>(
                    B2 + (size_t)kb * 1024 + (p * 32 + lane) * 8));
                b2r[2 * p][0] = v.x; b2r[2 * p][1] = v.y;
                b2r[2 * p + 1][0] = v.z; b2r[2 * p + 1][1] = v.w;
            }
            #pragma unroll
            for (int ni = 0; ni < 8; ni++)
                mma_f16(a2cc[ni][0], a2cc[ni][1], a2cc[ni][2], a2cc[ni][3],
                        a0, a1, a2, a3, b2r[ni][0], b2r[ni][1]);
        }
        float* o = outFused + ((size_t)s * BATCH + mt * 128 + wid * 16) * 64;
        #pragma unroll
        for (int ni = 0; ni < 8; ni++) {
            int c = ni * 8 + 2 * t4;
            red_add_v2(&o[g * 64 + c],       a2cc[ni][0], a2cc[ni][1]);
            red_add_v2(&o[(g + 8) * 64 + c], a2cc[ni][2], a2cc[ni][3]);
        }
    }
}

// ------------------------------------------------------------------- host --
extern "C" void kernel_launch(void* const* d_in, const int* in_sizes, int n_in,
                              void* d_out, int out_size)
{
    const float* x    = (const float*)d_in[0];
    const float* wm0  = (const float*)d_in[1];
    const float* wls0 = (const float*)d_in[2];
    const float* bm0  = (const float*)d_in[3];
    const float* bls0 = (const float*)d_in[4];
    const float* zw0  = (const float*)d_in[5];
    const float* zb0  = (const float*)d_in[6];
    const float* wm1  = (const float*)d_in[7];
    const float* wls1 = (const float*)d_in[8];
    const float* bm1  = (const float*)d_in[9];
    const float* bls1 = (const float*)d_in[10];
    const float* zw1  = (const float*)d_in[11];
    const float* zb1  = (const float*)d_in[12];
    const float* wm2  = (const float*)d_in[13];
    const float* wls2 = (const float*)d_in[14];
    const float* bm2  = (const float*)d_in[15];
    const float* bls2 = (const float*)d_in[16];
    const float* zw2  = (const float*)d_in[17];
    const float* zb2  = (const float*)d_in[18];

    __half *h0, *xpk, *wt0, *wt1, *wt2;
    float *bias, *sig;
    cudaGetSymbolAddress((void**)&h0,  g_h0);
    cudaGetSymbolAddress((void**)&xpk, g_xpk);
    cudaGetSymbolAddress((void**)&wt0, g_wt0);
    cudaGetSymbolAddress((void**)&wt1, g_wt1);
    cudaGetSymbolAddress((void**)&wt2, g_wt2);
    cudaGetSymbolAddress((void**)&bias, g_bias);
    cudaGetSymbolAddress((void**)&sig,  g_sig);

    // Lazily created host-side objects (no device memory). Initialized on the
    // correctness call; reused identically on every capture/replay.
    static cudaStream_t s_side = nullptr;
    static cudaEvent_t  s_fork = nullptr, s_join = nullptr;
    if (!s_side) {
        cudaStreamCreateWithFlags(&s_side, cudaStreamNonBlocking);
        cudaEventCreateWithFlags(&s_fork, cudaEventDisableTiming);
        cudaEventCreateWithFlags(&s_join, cudaEventDisableTiming);
    }

    const int SMEM_BIG = 3 * (128 * 64 + 128 * 64) * 2;    // 98304
    cudaFuncSetAttribute(gemm_f16k<128, 2, 4, true, true,  false>,
                         cudaFuncAttributeMaxDynamicSharedMemorySize, SMEM_BIG);
    cudaFuncSetAttribute(gemm_f16k<128, 2, 4, true, false, true >,
                         cudaFuncAttributeMaxDynamicSharedMemorySize, SMEM_BIG);

    // ---- sig = exp(log_std) once (sample-independent)
    sig_precompute_kernel<<<(SIG_TOTAL + 255) / 256, 256>>>(
        wls0, wls1, wls2, bls0, bls1, bls2);

    // ---- fork: wt1/wt2 packs (needed only by L1) run beside L0
    cudaEventRecord(s_fork, 0);
    cudaStreamWaitEvent(s_side, s_fork, 0);
    pack_w_kernel<<<dim3(512 / 32, 512 / 32, NS), 256, 0, s_side>>>(
        zw1, sig + SIG_W1, wm1, wt1, 512, 512, 128);
    pack_w_kernel<<<dim3(64 / 32, 512 / 32, NS), 256, 0, s_side>>>(
        zw2, sig + SIG_W2, wm2, wt2, 512, 64, 64);
    cudaEventRecord(s_join, s_side);

    // ---- main stream: L0 dependencies, then L0
    pack_x_kernel<<<256, 256>>>(x, xpk);
    pack_w_kernel<<<dim3(512 / 32, 256 / 32, NS), 256>>>(
        zw0, sig + SIG_W0, wm0, wt0, 256, 512, 128);
    pack_bias_kernel<<<(NS * 1088 + 255) / 256, 256>>>(zb0, bm0, zb1, bm1, zb2, bm2);
    out_init_kernel<<<(NS * BATCH * 64) / 256, 256>>>((float*)d_out, bias + 32768);

    gemm_f16k<128, 2, 4, true, true, false><<<dim3(4, 16, NS), 256, SMEM_BIG>>>(
        xpk, 0, wt0, (size_t)256 * 512,
        bias, 512, nullptr, h0, nullptr, nullptr, /*KC=*/16, /*KCnext=*/32);

    // ---- join, then L1 (+fused L2)
    cudaStreamWaitEvent(0, s_join, 0);
    gemm_f16k<128, 2, 4, true, false, true><<<dim3(4, 16, NS), 256, SMEM_BIG>>>(
        h0, (size_t)BATCH * 512, wt1, (size_t)512 * 512,
        bias + 16384, 512, nullptr, nullptr, wt2, (float*)d_out,
        /*KC=*/32, /*KCnext=*/0);
}

// round 17
// speedup vs baseline: 1.0208x; 1.0006x over previous
#include <cuda_runtime.h>
#include <cuda_fp16.h>
#include <cstdint>

// ---------------------------------------------------------------------------
// BayesianNN (sm_103 target, legacy mma path):
// out[s] = L2( tanh(L1( tanh(L0(x)) )) ),  Li: h @ (z_w*e^ls + m) + bias
// S=32, B=2048, dims 256 -> 512 -> 512 -> 64, fp32 in/out.
//
// Round 17 (= round 15 resubmit; two infra failures, not kernel failures):
// empty the critical path ahead of L0. Side stream carries pack_x +
// pack_bias (inline expf) + out_init + wt1/wt2 packs; main stream is
// sig -> pack_w0 -> L0 -> L1. GEMMs unchanged (at legacy HMMA roofline
// ~287 TF/s): fp16 fragment-packed, K=64 stages, fused L2 with
// red.v2.f32 split-K.
// ---------------------------------------------------------------------------

#define NS 32
#define BATCH 2048

__device__ __align__(1024) __half g_h0[(size_t)NS * BATCH * 512];  // 64 MB
__device__ __align__(1024) __half g_xpk[BATCH * 256];              // 1 MB
__device__ __align__(1024) __half g_wt0[NS * 256 * 512];           // 8 MB
__device__ __align__(1024) __half g_wt1[NS * 512 * 512];           // 16 MB
__device__ __align__(1024) __half g_wt2[NS * 512 * 64];            // 2 MB
__device__ float g_bias[NS * (512 + 512 + 64)];

// Precomputed exp(log_std) for WEIGHTS only (biases inline now).
#define SIG_W0 0
#define SIG_W1 131072
#define SIG_W2 393216
#define SIG_WTOT 425984
__device__ float g_sig[SIG_WTOT];

// ---------------------------------------------------------------- helpers --
__device__ __forceinline__ float fast_tanh(float x) {
    float t = __expf(2.0f * x);
    return 1.0f - __fdividef(2.0f, t + 1.0f);
}

__device__ __forceinline__ void cp_async16(void* smem_dst, const void* gmem_src) {
    unsigned s = (unsigned)__cvta_generic_to_shared(smem_dst);
    asm volatile("cp.async.cg.shared.global [%0], [%1], 16;\n"
                 :: "r"(s), "l"(gmem_src));
}
__device__ __forceinline__ void cp_commit() {
    asm volatile("cp.async.commit_group;\n" ::: "memory");
}
template<int N>
__device__ __forceinline__ void cp_wait() {
    asm volatile("cp.async.wait_group %0;\n" :: "n"(N) : "memory");
}

__device__ __forceinline__ void mma_f16(
    float& d0, float& d1, float& d2, float& d3,
    uint32_t a0, uint32_t a1, uint32_t a2, uint32_t a3,
    uint32_t b0, uint32_t b1)
{
    asm volatile(
        "mma.sync.aligned.m16n8k16.row.col.f32.f16.f16.f32 "
        "{%0,%1,%2,%3}, {%4,%5,%6,%7}, {%8,%9}, {%0,%1,%2,%3};"
        : "+f"(d0), "+f"(d1), "+f"(d2), "+f"(d3)
        : "r"(a0), "r"(a1), "r"(a2), "r"(a3), "r"(b0), "r"(b1));
}

__device__ __forceinline__ void red_add_v2(float* addr, float v0, float v1) {
    asm volatile("red.global.add.v2.f32 [%0], {%1, %2};"
                 :: "l"(addr), "f"(v0), "f"(v1) : "memory");
}

__device__ __forceinline__ uint32_t h2u(__half2 h) {
    return *reinterpret_cast<uint32_t*>(&h);
}

// ------------------------------------------------------------ pack kernels --
// sig = exp(log_std) for the three weight matrices (sample-independent).
__global__ __launch_bounds__(256) void sig_precompute_kernel(
    const float* __restrict__ wls0, const float* __restrict__ wls1,
    const float* __restrict__ wls2)
{
    int i = blockIdx.x * 256 + threadIdx.x;
    if (i >= SIG_WTOT) return;
    float v;
    if      (i < SIG_W1)   v = wls0[i - SIG_W0];
    else if (i < SIG_W2)   v = wls1[i - SIG_W1];
    else                   v = wls2[i - SIG_W2];
    g_sig[i] = __expf(v);
}

// A fragment image: per (mtile[128 rows], kc16) block of 4KB:
//   [sub16 (8)][lane (32)][a0,a1,a2,a3 (16B)]
__global__ __launch_bounds__(256) void pack_x_kernel(
    const float* __restrict__ x, __half* __restrict__ out)
{
    int t = blockIdx.x * 256 + threadIdx.x;      // 65536 fragments
    int lane = t & 31, sub16 = (t >> 5) & 7, kc = (t >> 8) & 15, mt = t >> 12;
    int g = lane >> 2, t4 = lane & 3;
    int m = mt * 128 + sub16 * 16 + g;
    int k = kc * 16 + 2 * t4;
    float2 v00 = *reinterpret_cast<const float2*>(&x[(size_t)m * 256 + k]);
    float2 v01 = *reinterpret_cast<const float2*>(&x[(size_t)m * 256 + k + 8]);
    float2 v10 = *reinterpret_cast<const float2*>(&x[(size_t)(m + 8) * 256 + k]);
    float2 v11 = *reinterpret_cast<const float2*>(&x[(size_t)(m + 8) * 256 + k + 8]);
    uint4 w;
    w.x = h2u(__float22half2_rn(v00));
    w.y = h2u(__float22half2_rn(v10));
    w.z = h2u(__float22half2_rn(v01));
    w.w = h2u(__float22half2_rn(v11));
    *reinterpret_cast<uint4*>(out + (size_t)t * 8) = w;
}

// B fragment image, PAIR-PACKED: per (ntile[BN], kc16) block of BN*16 halves.
__global__ __launch_bounds__(256) void pack_w_kernel(
    const float* __restrict__ zw, const float* __restrict__ sigw,
    const float* __restrict__ wm, __half* __restrict__ out,
    int K, int N, int BN)
{
    __shared__ float tile[32][33];
    const int n0 = blockIdx.x * 32, k0 = blockIdx.y * 32, s = blockIdx.z;
    const int t = threadIdx.x;
    {
        int kk = t >> 3, nn4 = (t & 7) * 4;
        size_t io = (size_t)(k0 + kk) * N + n0 + nn4;
        float4 z = *reinterpret_cast<const float4*>(zw + (size_t)s * K * N + io);
        float4 sg = *reinterpret_cast<const float4*>(sigw + io);
        float4 m = *reinterpret_cast<const float4*>(wm + io);
        tile[kk][nn4 + 0] = fmaf(z.x, sg.x, m.x);
        tile[kk][nn4 + 1] = fmaf(z.y, sg.y, m.y);
        tile[kk][nn4 + 2] = fmaf(z.z, sg.z, m.z);
        tile[kk][nn4 + 3] = fmaf(z.w, sg.w, m.w);
    }
    __syncthreads();
    {
        int kc_loc = t >> 7, n8_loc = (t >> 5) & 3, lane = t & 31;
        int g = lane >> 2, t4 = lane & 3;
        int kr = kc_loc * 16 + 2 * t4;
        int nc = n8_loc * 8 + g;
        float b00 = tile[kr][nc],     b01 = tile[kr + 1][nc];
        float b10 = tile[kr + 8][nc], b11 = tile[kr + 9][nc];
        uint2 w;
        w.x = h2u(__float22half2_rn(make_float2(b00, b01)));
        w.y = h2u(__float22half2_rn(make_float2(b10, b11)));
        int n_g = n0 + n8_loc * 8;
        int nt = n_g / BN, n8b = (n_g % BN) >> 3;
        int kc_g = (k0 >> 4) + kc_loc;
        size_t blk = ((size_t)(s * (N / BN) + nt) * (K >> 4) + kc_g)
                     * (size_t)(BN * 16);
        size_t off = ((size_t)((n8b >> 1) * 32 + lane)) * 8 + (n8b & 1) * 4;
        *reinterpret_cast<uint2*>(out + blk + off) = w;
    }
}

// Bias materialization with INLINE expf (no sig dependency -> side stream).
__global__ __launch_bounds__(256) void pack_bias_kernel(
    const float* __restrict__ zb0, const float* __restrict__ bls0, const float* __restrict__ bm0,
    const float* __restrict__ zb1, const float* __restrict__ bls1, const float* __restrict__ bm1,
    const float* __restrict__ zb2, const float* __restrict__ bls2, const float* __restrict__ bm2)
{
    int i = blockIdx.x * 256 + threadIdx.x;
    if (i >= NS * 1088) return;
    float v;
    if (i < 16384)      { int n = i & 511;                v = fmaf(zb0[i], __expf(bls0[n]), bm0[n]); }
    else if (i < 32768) { int j = i - 16384, n = j & 511; v = fmaf(zb1[j], __expf(bls1[n]), bm1[n]); }
    else                { int j = i - 32768, n = j & 63;  v = fmaf(zb2[j], __expf(bls2[n]), bm2[n]); }
    g_bias[i] = v;
}

// Initialize d_out with the L2 bias (split-K partials RED on top of it).
__global__ __launch_bounds__(256) void out_init_kernel(
    float* __restrict__ out, const float* __restrict__ zb2,
    const float* __restrict__ bls2, const float* __restrict__ bm2)
{
    int i = blockIdx.x * 256 + threadIdx.x;       // NS*BATCH*64 = 4194304
    int s = i >> 17, n = i & 63;
    out[i] = fmaf(__ldg(&zb2[s * 64 + n]), __expf(__ldg(&bls2[n])),
                  __ldg(&bm2[n]));
}

// ------------------------------------------------------------------- GEMM --
// D[s] (128 x BN) = A(128,K) @ W(K,BN) + bias, opt tanh.
// Stage = 64 K (four kc16 blocks), 3-stage cp.async pipeline.
template<int BN, int WM, int WN, bool TANH, bool PACKOUT, bool FUSE>
__global__ __launch_bounds__(256, 2) void gemm_f16k(
    const __half* __restrict__ Apk, size_t aStr,
    const __half* __restrict__ Bpk, size_t bStr,
    const float* __restrict__ bias, int bStride,
    float* __restrict__ outPlain, __half* __restrict__ outPk,
    const __half* __restrict__ B2pk, float* __restrict__ outFused,
    int KC, int KCnext)
{
    constexpr int MI = 8 / WM;
    constexpr int NI = (BN / WN) / 8;
    constexpr int ST_A = 128 * 64;        // halfs per A stage (16KB)
    constexpr int ST_B = BN * 64;
    constexpr int ST   = ST_A + ST_B;
    constexpr int A16  = 128 * 16;
    constexpr int B16  = BN * 16;
    extern __shared__ __align__(16) __half smem[];

    const int tid = threadIdx.x, wid = tid >> 5, lane = tid & 31;
    const int g = lane >> 2, t4 = lane & 3;
    const int s = blockIdx.z, nt = blockIdx.x, mt = blockIdx.y;
    const int wm16 = (wid / WN) * MI;
    const int wn8  = (wid % WN) * NI;

    const __half* Ab = Apk + (size_t)s * aStr + (size_t)mt * KC * A16;
    const __half* Bb = Bpk + (size_t)s * bStr + (size_t)nt * KC * B16;

    float acc[MI][NI][4];
    #pragma unroll
    for (int i = 0; i < MI; i++)
        #pragma unroll
        for (int j = 0; j < NI; j++)
            #pragma unroll
            for (int r = 0; r < 4; r++) acc[i][j][r] = 0.0f;

    const int KS = KC >> 2;

    auto issue = [&](int ks, int st) {
        __half* As = smem + st * ST;
        __half* Bs = As + ST_A;
        #pragma unroll
        for (int i = 0; i < ST_A / (256 * 8); i++)
            cp_async16(As + (tid + i * 256) * 8,
                       Ab + (size_t)ks * ST_A + (tid + i * 256) * 8);
        #pragma unroll
        for (int i = 0; i < ST_B / (256 * 8); i++)
            cp_async16(Bs + (tid + i * 256) * 8,
                       Bb + (size_t)ks * ST_B + (tid + i * 256) * 8);
        cp_commit();
    };

    issue(0, 0);
    if (KS > 1) issue(1, 1);

    for (int ks = 0; ks < KS; ks++) {
        if (ks >= KS - 2) cp_wait<0>(); else cp_wait<1>();
        __syncthreads();
        if (ks + 2 < KS) issue(ks + 2, (ks + 2) % 3);

        const __half* Asb = smem + (ks % 3) * ST;
        #pragma unroll
        for (int kb = 0; kb < 4; kb++) {
            const __half* As = Asb + kb * A16;
            const __half* Bs = Asb + ST_A + kb * B16;

            uint32_t aR[MI][4];
            #pragma unroll
            for (int mi = 0; mi < MI; mi++) {
                const uint4 v = *reinterpret_cast<const uint4*>(
                    As + ((wm16 + mi) * 32 + lane) * 8);
                aR[mi][0] = v.x; aR[mi][1] = v.y; aR[mi][2] = v.z; aR[mi][3] = v.w;
            }
            uint32_t bR[NI][2];
            #pragma unroll
            for (int p = 0; p < NI / 2; p++) {
                const uint4 v = *reinterpret_cast<const uint4*>(
                    Bs + (((wn8 >> 1) + p) * 32 + lane) * 8);
                bR[2 * p][0] = v.x; bR[2 * p][1] = v.y;
                bR[2 * p + 1][0] = v.z; bR[2 * p + 1][1] = v.w;
            }
            #pragma unroll
            for (int mi = 0; mi < MI; mi++)
                #pragma unroll
                for (int ni = 0; ni < NI; ni++)
                    mma_f16(acc[mi][ni][0], acc[mi][ni][1],
                            acc[mi][ni][2], acc[mi][ni][3],
                            aR[mi][0], aR[mi][1], aR[mi][2], aR[mi][3],
                            bR[ni][0], bR[ni][1]);
        }
    }
    __syncthreads();

    // ---- epilogue
    if (!PACKOUT && !FUSE) {
        #pragma unroll
        for (int ni = 0; ni < NI; ni++) {
            int c = wn8 * 8 + ni * 8 + 2 * t4;
            float b0 = __ldg(&bias[(size_t)s * bStride + nt * BN + c]);
            float b1 = __ldg(&bias[(size_t)s * bStride + nt * BN + c + 1]);
            #pragma unroll
            for (int mi = 0; mi < MI; mi++) {
                int r = (wm16 + mi) * 16 + g;
                float v0 = acc[mi][ni][0] + b0, v1 = acc[mi][ni][1] + b1;
                float v2 = acc[mi][ni][2] + b0, v3 = acc[mi][ni][3] + b1;
                if (TANH) { v0 = fast_tanh(v0); v1 = fast_tanh(v1);
                            v2 = fast_tanh(v2); v3 = fast_tanh(v3); }
                size_t base = ((size_t)s * BATCH + mt * 128) * BN;
                *reinterpret_cast<float2*>(outPlain + base + (size_t)r * BN + c) =
                    make_float2(v0, v1);
                *reinterpret_cast<float2*>(outPlain + base + (size_t)(r + 8) * BN + c) =
                    make_float2(v2, v3);
            }
        }
        return;
    }

    // staged epilogue: phase 1 -> smem fp32 [128][BN+4] with bias + tanh
    float* stg = reinterpret_cast<float*>(smem);
    constexpr int SSTR = BN + 4;
    #pragma unroll
    for (int ni = 0; ni < NI; ni++) {
        int c = wn8 * 8 + ni * 8 + 2 * t4;
        float b0 = __ldg(&bias[(size_t)s * bStride + nt * BN + c]);
        float b1 = __ldg(&bias[(size_t)s * bStride + nt * BN + c + 1]);
        #pragma unroll
        for (int mi = 0; mi < MI; mi++) {
            int r = (wm16 + mi) * 16 + g;
            float v0 = acc[mi][ni][0] + b0, v1 = acc[mi][ni][1] + b1;
            float v2 = acc[mi][ni][2] + b0, v3 = acc[mi][ni][3] + b1;
            if (TANH) { v0 = fast_tanh(v0); v1 = fast_tanh(v1);
                        v2 = fast_tanh(v2); v3 = fast_tanh(v3); }
            *reinterpret_cast<float2*>(&stg[r * SSTR + c]) = make_float2(v0, v1);
            *reinterpret_cast<float2*>(&stg[(r + 8) * SSTR + c]) = make_float2(v2, v3);
        }
    }
    __syncthreads();

    if (PACKOUT) {
        #pragma unroll
        for (int ff = 0; ff < BN / 16; ff++) {
            int sub16 = tid >> 5;
            int r0 = sub16 * 16 + g;
            int c0 = ff * 16 + 2 * t4;
            float2 p00 = *reinterpret_cast<const float2*>(&stg[r0 * SSTR + c0]);
            float2 p10 = *reinterpret_cast<const float2*>(&stg[(r0 + 8) * SSTR + c0]);
            float2 p01 = *reinterpret_cast<const float2*>(&stg[r0 * SSTR + c0 + 8]);
            float2 p11 = *reinterpret_cast<const float2*>(&stg[(r0 + 8) * SSTR + c0 + 8]);
            uint4 w;
            w.x = h2u(__float22half2_rn(p00));
            w.y = h2u(__float22half2_rn(p10));
            w.z = h2u(__float22half2_rn(p01));
            w.w = h2u(__float22half2_rn(p11));
            size_t blk = ((size_t)(s * (BATCH / 128) + mt) * KCnext
                          + nt * (BN / 16) + ff) * (size_t)(128 * 16);
            *reinterpret_cast<uint4*>(outPk + blk + (size_t)tid * 8) = w;
        }
    }

    if (FUSE) {
        const __half* B2 = B2pk + (size_t)s * (512 * 64)
                         + (size_t)(nt * 8) * 1024;
        float a2cc[8][4];
        #pragma unroll
        for (int ni = 0; ni < 8; ni++)
            #pragma unroll
            for (int r = 0; r < 4; r++) a2cc[ni][r] = 0.0f;

        #pragma unroll
        for (int kb = 0; kb < 8; kb++) {
            int r0 = wid * 16 + g;
            int c0 = kb * 16 + 2 * t4;
            float2 p00 = *reinterpret_cast<const float2*>(&stg[r0 * SSTR + c0]);
            float2 p10 = *reinterpret_cast<const float2*>(&stg[(r0 + 8) * SSTR + c0]);
            float2 p01 = *reinterpret_cast<const float2*>(&stg[r0 * SSTR + c0 + 8]);
            float2 p11 = *reinterpret_cast<const float2*>(&stg[(r0 + 8) * SSTR + c0 + 8]);
            uint32_t a0 = h2u(__float22half2_rn(p00));
            uint32_t a1 = h2u(__float22half2_rn(p10));
            uint32_t a2 = h2u(__float22half2_rn(p01));
            uint32_t a3 = h2u(__float22half2_rn(p11));
            uint32_t b2r[8][2];
            #pragma unroll
            for (int p = 0; p < 4; p++) {
                const uint4 v = __ldg(reinterpret_cast<const uint4*>(
                    B2 + (size_t)kb * 1024 + (p * 32 + lane) * 8));
                b2r[2 * p][0] = v.x; b2r[2 * p][1] = v.y;
                b2r[2 * p + 1][0] = v.z; b2r[2 * p + 1][1] = v.w;
            }
            #pragma unroll
            for (int ni = 0; ni < 8; ni++)
                mma_f16(a2cc[ni][0], a2cc[ni][1], a2cc[ni][2], a2cc[ni][3],
                        a0, a1, a2, a3, b2r[ni][0], b2r[ni][1]);
        }
        float* o = outFused + ((size_t)s * BATCH + mt * 128 + wid * 16) * 64;
        #pragma unroll
        for (int ni = 0; ni < 8; ni++) {
            int c = ni * 8 + 2 * t4;
            red_add_v2(&o[g * 64 + c],       a2cc[ni][0], a2cc[ni][1]);
            red_add_v2(&o[(g + 8) * 64 + c], a2cc[ni][2], a2cc[ni][3]);
        }
    }
}

// ------------------------------------------------------------------- host --
extern "C" void kernel_launch(void* const* d_in, const int* in_sizes, int n_in,
                              void* d_out, int out_size)
{
    const float* x    = (const float*)d_in[0];
    const float* wm0  = (const float*)d_in[1];
    const float* wls0 = (const float*)d_in[2];
    const float* bm0  = (const float*)d_in[3];
    const float* bls0 = (const float*)d_in[4];
    const float* zw0  = (const float*)d_in[5];
    const float* zb0  = (const float*)d_in[6];
    const float* wm1  = (const float*)d_in[7];
    const float* wls1 = (const float*)d_in[8];
    const float* bm1  = (const float*)d_in[9];
    const float* bls1 = (const float*)d_in[10];
    const float* zw1  = (const float*)d_in[11];
    const float* zb1  = (const float*)d_in[12];
    const float* wm2  = (const float*)d_in[13];
    const float* wls2 = (const float*)d_in[14];
    const float* bm2  = (const float*)d_in[15];
    const float* bls2 = (const float*)d_in[16];
    const float* zw2  = (const float*)d_in[17];
    const float* zb2  = (const float*)d_in[18];

    __half *h0, *xpk, *wt0, *wt1, *wt2;
    float *bias, *sig;
    cudaGetSymbolAddress((void**)&h0,  g_h0);
    cudaGetSymbolAddress((void**)&xpk, g_xpk);
    cudaGetSymbolAddress((void**)&wt0, g_wt0);
    cudaGetSymbolAddress((void**)&wt1, g_wt1);
    cudaGetSymbolAddress((void**)&wt2, g_wt2);
    cudaGetSymbolAddress((void**)&bias, g_bias);
    cudaGetSymbolAddress((void**)&sig,  g_sig);

    static cudaStream_t s_side = nullptr;
    static cudaEvent_t  s_fork = nullptr, s_sig = nullptr, s_w = nullptr;
    if (!s_side) {
        cudaStreamCreateWithFlags(&s_side, cudaStreamNonBlocking);
        cudaEventCreateWithFlags(&s_fork, cudaEventDisableTiming);
        cudaEventCreateWithFlags(&s_sig,  cudaEventDisableTiming);
        cudaEventCreateWithFlags(&s_w,    cudaEventDisableTiming);
    }

    const int SMEM_BIG = 3 * (128 * 64 + 128 * 64) * 2;    // 98304
    cudaFuncSetAttribute(gemm_f16k<128, 2, 4, true, true,  false>,
                         cudaFuncAttributeMaxDynamicSharedMemorySize, SMEM_BIG);
    cudaFuncSetAttribute(gemm_f16k<128, 2, 4, true, false, true >,
                         cudaFuncAttributeMaxDynamicSharedMemorySize, SMEM_BIG);

    // ---- fork side stream at entry
    cudaEventRecord(s_fork, 0);
    cudaStreamWaitEvent(s_side, s_fork, 0);

    // main: sig -> pack_w0 -> pack_x -> pack_bias (main keeps L0's deps so
    // no extra join event is needed before L0; pack_x+bias are only ~4us)
    sig_precompute_kernel<<<(SIG_WTOT + 255) / 256, 256>>>(wls0, wls1, wls2);
    cudaEventRecord(s_sig, 0);
    pack_w_kernel<<<dim3(512 / 32, 256 / 32, NS), 256>>>(
        zw0, sig + SIG_W0, wm0, wt0, 256, 512, 128);
    pack_x_kernel<<<256, 256>>>(x, xpk);
    pack_bias_kernel<<<(NS * 1088 + 255) / 256, 256>>>(
        zb0, bls0, bm0, zb1, bls1, bm1, zb2, bls2, bm2);

    // side: out_init (independent) then, after sig, wt1/wt2 packs under L0
    out_init_kernel<<<(NS * BATCH * 64) / 256, 256, 0, s_side>>>(
        (float*)d_out, zb2, bls2, bm2);
    cudaStreamWaitEvent(s_side, s_sig, 0);
    pack_w_kernel<<<dim3(512 / 32, 512 / 32, NS), 256, 0, s_side>>>(
        zw1, sig + SIG_W1, wm1, wt1, 512, 512, 128);
    pack_w_kernel<<<dim3(64 / 32, 512 / 32, NS), 256, 0, s_side>>>(
        zw2, sig + SIG_W2, wm2, wt2, 512, 64, 64);
    cudaEventRecord(s_w, s_side);

    // main: L0 (needs xpk, wt0, bias — all on main stream already)
    gemm_f16k<128, 2, 4, true, true, false><<<dim3(4, 16, NS), 256, SMEM_BIG>>>(
        xpk, 0, wt0, (size_t)256 * 512,
        bias, 512, nullptr, h0, nullptr, nullptr, /*KC=*/16, /*KCnext=*/32);

    // main: L1 (+fused L2) after wt1/wt2 (and out_init) ready
    cudaStreamWaitEvent(0, s_w, 0);
    gemm_f16k<128, 2, 4, true, false, true><<<dim3(4, 16, NS), 256, SMEM_BIG>>>(
        h0, (size_t)BATCH * 512, wt1, (size_t)512 * 512,
        bias + 16384, 512, nullptr, nullptr, wt2, (float*)d_out,
        /*KC=*/32, /*KCnext=*/0);
}